// round 8
// baseline (speedup 1.0000x reference)
#include <cuda_runtime.h>
#include <cuda_bf16.h>
#include <cstdint>

// Sinkhorn OT, B=1024, N=M=256, 100 iters. One CTA (512 threads) per batch.
// mma.sync.m16n8k16 bf16 formulation; warp w (wr,wc) owns K rows 64wr..+64,
// cols 64wc..+64.
//   matvec1 (K^T u): A-frags of K^T held in registers (loaded once);
//                    B = u broadcast. 16 MMA/warp.
//   matvec2 (K v):   A-frags of K = contiguous words of row-major smem K
//                    (conflict-free LDS); B = v broadcast. 16 MMA/warp.
// Partials stored transposed (out*4+part) -> epilogue reduces via one LDS.128.

#define B_TOT   1024
#define ITERS   100
#define INV_EPS 10.0f
#define EPS_DIV 1e-8f

#define ROWW_W  132                        // words per padded K row
#define KROW_H  264                        // bf16 per padded K row
#define OFF_A   (256*ROWW_W*4)             // 135168
#define OFF_B   (OFF_A + 1024)
#define OFF_U   (OFF_B + 1024)
#define OFF_V   (OFF_U + 1024)
#define OFF_UBF (OFF_V + 1024)             // bf16[256]
#define OFF_VBF (OFF_UBF + 512)            // bf16[256]
#define OFF_PS  (OFF_VBF + 512)            // float[1024]
#define SMEM_BYTES (OFF_PS + 4096)         // 144640

__device__ float g_cost[B_TOT];

__device__ __forceinline__ float bflo(unsigned int p) { return __uint_as_float(p << 16); }
__device__ __forceinline__ float bfhi(unsigned int p) { return __uint_as_float(p & 0xffff0000u); }

__device__ __forceinline__ void mma16816(float& d0, float& d1, float& d2, float& d3,
                                         uint32_t a0, uint32_t a1, uint32_t a2, uint32_t a3,
                                         uint32_t b0, uint32_t b1) {
    asm volatile("mma.sync.aligned.m16n8k16.row.col.f32.bf16.bf16.f32 "
                 "{%0,%1,%2,%3}, {%4,%5,%6,%7}, {%8,%9}, {%0,%1,%2,%3};"
                 : "+f"(d0), "+f"(d1), "+f"(d2), "+f"(d3)
                 : "r"(a0), "r"(a1), "r"(a2), "r"(a3), "r"(b0), "r"(b1));
}

// pack K[r][c], K[r+1][c] (bf16 bits) into one b32 (lo = row r)
__device__ __forceinline__ uint32_t ld2k(const unsigned short* sK, int r, int c) {
    uint32_t lo = sK[r * KROW_H + c];
    uint32_t hi = sK[(r + 1) * KROW_H + c];
    return lo | (hi << 16);
}

extern __shared__ unsigned char smem_raw[];

__global__ __launch_bounds__(512, 1)
void sinkhorn_kernel(const float* __restrict__ C,
                     const float* __restrict__ mass_pred,
                     const float* __restrict__ mass_target)
{
    unsigned short* sK = (unsigned short*)smem_raw;            // 256 x 264 bf16
    const unsigned int* sKw = (const unsigned int*)smem_raw;   // word view
    float* s_a  = (float*)(smem_raw + OFF_A);
    float* s_b  = (float*)(smem_raw + OFF_B);
    float* s_u  = (float*)(smem_raw + OFF_U);
    float* s_v  = (float*)(smem_raw + OFF_V);
    __nv_bfloat16* s_ubf = (__nv_bfloat16*)(smem_raw + OFF_UBF);
    __nv_bfloat16* s_vbf = (__nv_bfloat16*)(smem_raw + OFF_VBF);
    const uint32_t* ubf_w = (const uint32_t*)(smem_raw + OFF_UBF);
    const uint32_t* vbf_w = (const uint32_t*)(smem_raw + OFF_VBF);
    float* s_ps = (float*)(smem_raw + OFF_PS);

    const int b    = blockIdx.x;
    const int t    = threadIdx.x;
    const int w    = t >> 5;
    const int lane = t & 31;
    const int lq   = lane >> 2;     // 0..7
    const int lr   = lane & 3;      // 0..3
    const int wr   = w >> 2;        // K row-block
    const int wc   = w & 3;         // K col-block
    const float* __restrict__ Cb = C + (size_t)b * 65536;

    // ---------- Build K = exp(-C/eps) (bf16, padded rows) ----------
    #pragma unroll 4
    for (int k = 0; k < 32; k++) {
        int idx4 = k * 512 + t;
        float4 c = ((const float4*)Cb)[idx4];
        int lin = idx4 << 2;
        int n = lin >> 8;
        int m = lin & 255;
        __nv_bfloat162 p0 = __floats2bfloat162_rn(__expf(-c.x * INV_EPS),
                                                  __expf(-c.y * INV_EPS));
        __nv_bfloat162 p1 = __floats2bfloat162_rn(__expf(-c.z * INV_EPS),
                                                  __expf(-c.w * INV_EPS));
        *(__nv_bfloat162*)&sK[n * KROW_H + m]     = p0;
        *(__nv_bfloat162*)&sK[n * KROW_H + m + 2] = p1;
    }

    // ---------- Normalize masses (threads 0-255), s_ps scratch ----------
    if (t < 256) {
        float mpv = mass_pred[b * 256 + t];
        float mtv = mass_target[b * 256 + t];
        float sa = mpv, sb = mtv;
        #pragma unroll
        for (int o = 16; o; o >>= 1) {
            sa += __shfl_xor_sync(0xffffffffu, sa, o);
            sb += __shfl_xor_sync(0xffffffffu, sb, o);
        }
        if ((t & 31) == 0) { s_ps[t >> 5] = sa; s_ps[8 + (t >> 5)] = sb; }
        s_ps[64 + t]  = mpv;
        s_ps[320 + t] = mtv;
    }
    // init u0 = 1 (bf16 0x3F80 pairs)
    if (t < 128) ((uint32_t*)(smem_raw + OFF_UBF))[t] = 0x3F803F80u;
    __syncthreads();
    if (t < 256) {
        float suma = 0.f, sumb = 0.f;
        #pragma unroll
        for (int q = 0; q < 8; q++) { suma += s_ps[q]; sumb += s_ps[8 + q]; }
        s_a[t] = s_ps[64 + t]  / (suma + EPS_DIV);
        s_b[t] = s_ps[320 + t] / (sumb + EPS_DIV);
        s_u[t] = 1.0f;
    }
    __syncthreads();

    // ---------- Load A-fragments of K^T (this warp's 64x64 block) ----------
    // Tile (mt,kt): m = K-col 64wc+16mt.., k = K-row 64wr+16kt..
    uint32_t af[4][4][4];
    #pragma unroll
    for (int mt = 0; mt < 4; mt++) {
        #pragma unroll
        for (int kt = 0; kt < 4; kt++) {
            int mb = 64*wc + 16*mt + lq;      // K column
            int kb = 64*wr + 16*kt + 2*lr;    // K row
            af[mt][kt][0] = ld2k(sK, kb,     mb);
            af[mt][kt][1] = ld2k(sK, kb,     mb + 8);
            af[mt][kt][2] = ld2k(sK, kb + 8, mb);
            af[mt][kt][3] = ld2k(sK, kb + 8, mb + 8);
        }
    }
    __syncthreads();

    // ---------- 100 Sinkhorn iterations ----------
    for (int it = 0; it < ITERS; it++) {
        // ===== matvec1: Kt_u = K^T u  (A-frags in regs, B = u broadcast) =====
        #pragma unroll
        for (int mt = 0; mt < 4; mt++) {
            float d0 = 0.f, d1 = 0.f, d2 = 0.f, d3 = 0.f;
            #pragma unroll
            for (int kt = 0; kt < 4; kt++) {
                uint32_t b0 = ubf_w[32*wr + 8*kt + lr];
                uint32_t b1 = ubf_w[32*wr + 8*kt + lr + 4];
                mma16816(d0, d1, d2, d3,
                         af[mt][kt][0], af[mt][kt][1], af[mt][kt][2], af[mt][kt][3],
                         b0, b1);
            }
            if (lr == 0) {   // transposed partials: ps[out*4 + wr]
                s_ps[(64*wc + 16*mt + lq) * 4 + wr]     = d0;
                s_ps[(64*wc + 16*mt + lq + 8) * 4 + wr] = d2;
            }
        }
        __syncthreads();

        if (t < 256) {
            float4 p = *(const float4*)&s_ps[t * 4];
            float ktu = (p.x + p.y) + (p.z + p.w);
            float vv = __fdividef(s_b[t], ktu + EPS_DIV);
            s_v[t] = vv;
            s_vbf[t] = __float2bfloat16(vv);
        }
        __syncthreads();

        // ===== matvec2: K_v = K v  (A = K rows from smem words, B = v bcast) =====
        #pragma unroll
        for (int mt2 = 0; mt2 < 4; mt2++) {
            float d0 = 0.f, d1 = 0.f, d2 = 0.f, d3 = 0.f;
            int r0 = (64*wr + 16*mt2 + lq)     * ROWW_W + 32*wc;
            int r1 = (64*wr + 16*mt2 + lq + 8) * ROWW_W + 32*wc;
            #pragma unroll
            for (int kt2 = 0; kt2 < 4; kt2++) {
                uint32_t a0 = sKw[r0 + 8*kt2 + lr];
                uint32_t a1 = sKw[r1 + 8*kt2 + lr];
                uint32_t a2 = sKw[r0 + 8*kt2 + lr + 4];
                uint32_t a3 = sKw[r1 + 8*kt2 + lr + 4];
                uint32_t b0 = vbf_w[32*wc + 8*kt2 + lr];
                uint32_t b1 = vbf_w[32*wc + 8*kt2 + lr + 4];
                mma16816(d0, d1, d2, d3, a0, a1, a2, a3, b0, b1);
            }
            if (lr == 0) {   // transposed partials: ps[out*4 + wc]
                s_ps[(64*wr + 16*mt2 + lq) * 4 + wc]     = d0;
                s_ps[(64*wr + 16*mt2 + lq + 8) * 4 + wc] = d2;
            }
        }
        __syncthreads();

        if (t < 256) {
            float4 p = *(const float4*)&s_ps[t * 4];
            float kv = (p.x + p.y) + (p.z + p.w);
            float uu = __fdividef(s_a[t], kv + EPS_DIV);
            s_u[t] = uu;
            s_ubf[t] = __float2bfloat16(uu);
        }
        __syncthreads();
    }

    // ---------- ot_cost[b] = sum u[n] K[n,m] v[m] C[n,m] ----------
    float accf = 0.f;
    #pragma unroll 4
    for (int k = 0; k < 32; k++) {
        int idx4 = k * 512 + t;
        float4 c = ((const float4*)Cb)[idx4];
        int lin = idx4 << 2;
        int n = lin >> 8;
        int m = lin & 255;
        uint2 q = *(const uint2*)&sKw[n * ROWW_W + (m >> 1)];
        float un = s_u[n];
        float4 vv = *(const float4*)&s_v[m];
        accf += un * (bflo(q.x) * vv.x * c.x + bfhi(q.x) * vv.y * c.y
                    + bflo(q.y) * vv.z * c.z + bfhi(q.y) * vv.w * c.w);
    }
    #pragma unroll
    for (int o = 16; o; o >>= 1) accf += __shfl_xor_sync(0xffffffffu, accf, o);
    __syncthreads();
    if ((t & 31) == 0) s_ps[t >> 5] = accf;
    __syncthreads();
    if (t == 0) {
        float s = 0.f;
        #pragma unroll
        for (int q = 0; q < 16; q++) s += s_ps[q];
        g_cost[b] = s;
    }
}

__global__ void reduce_kernel(float* __restrict__ out)
{
    __shared__ float sm[8];
    int t = threadIdx.x;
    float s = 0.f;
    #pragma unroll
    for (int i = t; i < B_TOT; i += 256) s += g_cost[i];
    #pragma unroll
    for (int o = 16; o; o >>= 1) s += __shfl_xor_sync(0xffffffffu, s, o);
    if ((t & 31) == 0) sm[t >> 5] = s;
    __syncthreads();
    if (t == 0) {
        float tot = 0.f;
        #pragma unroll
        for (int q = 0; q < 8; q++) tot += sm[q];
        out[0] = tot * (1.0f / B_TOT);
    }
}

extern "C" void kernel_launch(void* const* d_in, const int* in_sizes, int n_in,
                              void* d_out, int out_size)
{
    const float* C  = (const float*)d_in[0];
    const float* mp = (const float*)d_in[1];
    const float* mt = (const float*)d_in[2];
    float* out = (float*)d_out;

    cudaFuncSetAttribute(sinkhorn_kernel,
                         cudaFuncAttributeMaxDynamicSharedMemorySize, SMEM_BYTES);

    sinkhorn_kernel<<<B_TOT, 512, SMEM_BYTES>>>(C, mp, mt);
    reduce_kernel<<<1, 256>>>(out);
}

// round 9
// speedup vs baseline: 1.0890x; 1.0890x over previous
#include <cuda_runtime.h>
#include <cuda_bf16.h>
#include <cstdint>

// Sinkhorn OT, B=1024, N=M=256, 100 iters. One CTA (512 threads) per batch.
// Warp w fully owns K-cols 16w..+15 (matvec1, A-frags of K^T in registers)
// and K-rows 16w..+15 (matvec2, A-frags = contiguous words of row-major smem
// K, conflict-free). No cross-warp reductions; 2 barriers/iter; in-warp divides.
// Vector operands use a permuted 4-copy bf16 layout (perm[36*lr + 2kt]) so
// all MMA B-loads are 1-wavefront LDS.128.

#define B_TOT   1024
#define ITERS   100
#define INV_EPS 10.0f
#define EPS_DIV 1e-8f

#define ROWW_W  132                        // words per padded K row
#define KROW_H  264                        // bf16 per padded K row
#define OFF_A   (256*ROWW_W*4)             // 135168
#define OFF_B   (OFF_A + 1024)
#define OFF_U   (OFF_B + 1024)
#define OFF_V   (OFF_U + 1024)
#define OFF_UP  (OFF_V + 1024)             // uperm: 160 words (640B)
#define OFF_VP  (OFF_UP + 640)             // vperm: 160 words
#define OFF_PS  (OFF_VP + 640)             // 576 floats scratch
#define SMEM_BYTES (OFF_PS + 2304)         // 142848

__device__ float g_cost[B_TOT];

__device__ __forceinline__ float bflo(unsigned int p) { return __uint_as_float(p << 16); }
__device__ __forceinline__ float bfhi(unsigned int p) { return __uint_as_float(p & 0xffff0000u); }

__device__ __forceinline__ void mma16816(float& d0, float& d1, float& d2, float& d3,
                                         uint32_t a0, uint32_t a1, uint32_t a2, uint32_t a3,
                                         uint32_t b0, uint32_t b1) {
    asm volatile("mma.sync.aligned.m16n8k16.row.col.f32.bf16.bf16.f32 "
                 "{%0,%1,%2,%3}, {%4,%5,%6,%7}, {%8,%9}, {%0,%1,%2,%3};"
                 : "+f"(d0), "+f"(d1), "+f"(d2), "+f"(d3)
                 : "r"(a0), "r"(a1), "r"(a2), "r"(a3), "r"(b0), "r"(b1));
}

// pack K[r][c], K[r+1][c] (bf16 bits) into one b32 (lo = row r)
__device__ __forceinline__ uint32_t ld2k(const unsigned short* sK, int r, int c) {
    uint32_t lo = sK[r * KROW_H + c];
    uint32_t hi = sK[(r + 1) * KROW_H + c];
    return lo | (hi << 16);
}

// Publish x0 (=vec[16w+lq]) / x1 (=vec[16w+lq+8]) into the permuted 4-copy
// bf16 layout: perm[36c + 2w + h] = {vec[16w+2c+8h], vec[16w+2c+8h+1]}.
__device__ __forceinline__ void publish_perm(uint32_t* perm, int w, int lane,
                                             float x0, float x1) {
    int c = (lane >> 1) & 3;
    int h = lane & 1;
    float s00 = __shfl_sync(0xffffffffu, x0, 8*c);
    float s01 = __shfl_sync(0xffffffffu, x0, 8*c + 4);
    float s10 = __shfl_sync(0xffffffffu, x1, 8*c);
    float s11 = __shfl_sync(0xffffffffu, x1, 8*c + 4);
    float lo = h ? s10 : s00;
    float hi = h ? s11 : s01;
    __nv_bfloat162 p = __floats2bfloat162_rn(lo, hi);
    if (lane < 8) perm[36*c + 2*w + h] = *(uint32_t*)&p;
}

extern __shared__ unsigned char smem_raw[];

__global__ __launch_bounds__(512, 1)
void sinkhorn_kernel(const float* __restrict__ C,
                     const float* __restrict__ mass_pred,
                     const float* __restrict__ mass_target)
{
    unsigned short* sK = (unsigned short*)smem_raw;            // 256 x 264 bf16
    const unsigned int* sKw = (const unsigned int*)smem_raw;   // word view
    float* s_a  = (float*)(smem_raw + OFF_A);
    float* s_b  = (float*)(smem_raw + OFF_B);
    float* s_u  = (float*)(smem_raw + OFF_U);
    float* s_v  = (float*)(smem_raw + OFF_V);
    uint32_t* uperm = (uint32_t*)(smem_raw + OFF_UP);
    uint32_t* vperm = (uint32_t*)(smem_raw + OFF_VP);
    const uint4* up4 = (const uint4*)(smem_raw + OFF_UP);
    const uint4* vp4 = (const uint4*)(smem_raw + OFF_VP);
    float* s_ps = (float*)(smem_raw + OFF_PS);

    const int b    = blockIdx.x;
    const int t    = threadIdx.x;
    const int w    = t >> 5;        // warp 0..15
    const int lane = t & 31;
    const int lq   = lane >> 2;     // 0..7
    const int lr   = lane & 3;      // 0..3
    const float* __restrict__ Cb = C + (size_t)b * 65536;

    // ---------- Build K = exp(-C/eps) (bf16, padded rows) ----------
    #pragma unroll 4
    for (int k = 0; k < 32; k++) {
        int idx4 = k * 512 + t;
        float4 c = ((const float4*)Cb)[idx4];
        int lin = idx4 << 2;
        int n = lin >> 8;
        int m = lin & 255;
        __nv_bfloat162 p0 = __floats2bfloat162_rn(__expf(-c.x * INV_EPS),
                                                  __expf(-c.y * INV_EPS));
        __nv_bfloat162 p1 = __floats2bfloat162_rn(__expf(-c.z * INV_EPS),
                                                  __expf(-c.w * INV_EPS));
        *(__nv_bfloat162*)&sK[n * KROW_H + m]     = p0;
        *(__nv_bfloat162*)&sK[n * KROW_H + m + 2] = p1;
    }

    // ---------- Normalize masses (threads 0-255), s_ps scratch ----------
    if (t < 256) {
        float mpv = mass_pred[b * 256 + t];
        float mtv = mass_target[b * 256 + t];
        float sa = mpv, sb = mtv;
        #pragma unroll
        for (int o = 16; o; o >>= 1) {
            sa += __shfl_xor_sync(0xffffffffu, sa, o);
            sb += __shfl_xor_sync(0xffffffffu, sb, o);
        }
        if ((t & 31) == 0) { s_ps[t >> 5] = sa; s_ps[8 + (t >> 5)] = sb; }
        s_ps[64 + t]  = mpv;
        s_ps[320 + t] = mtv;
    }
    // init uperm = all 1.0 bf16 pairs
    if (t < 160) uperm[t] = 0x3F803F80u;
    __syncthreads();
    if (t < 256) {
        float suma = 0.f, sumb = 0.f;
        #pragma unroll
        for (int q = 0; q < 8; q++) { suma += s_ps[q]; sumb += s_ps[8 + q]; }
        s_a[t] = s_ps[64 + t]  / (suma + EPS_DIV);
        s_b[t] = s_ps[320 + t] / (sumb + EPS_DIV);
        s_u[t] = 1.0f;
    }
    __syncthreads();

    // ---------- Persistent A-frags of K^T: warp's 16 cols x all 256 rows ----------
    // Tile kt: X = K^T[m=16w..+16][k=16kt..+16], row-major frags.
    uint32_t af[16][4];
    #pragma unroll
    for (int kt = 0; kt < 16; kt++) {
        int r = 16*kt + 2*lr;
        int c = 16*w + lq;
        af[kt][0] = ld2k(sK, r,     c);
        af[kt][1] = ld2k(sK, r,     c + 8);
        af[kt][2] = ld2k(sK, r + 8, c);
        af[kt][3] = ld2k(sK, r + 8, c + 8);
    }

    // Hoisted per-thread constants
    const float sa0 = s_a[16*w + lq];
    const float sa1 = s_a[16*w + lq + 8];
    const float sb0 = s_b[16*w + lq];
    const float sb1 = s_b[16*w + lq + 8];
    const int rA = (16*w + lq)     * ROWW_W;
    const int rB = (16*w + lq + 8) * ROWW_W;

    // ---------- 100 Sinkhorn iterations ----------
    for (int it = 0; it < ITERS; it++) {
        // ===== matvec1: Kt_u for cols 16w..+15 (af as A, u-perm as B) =====
        {
            float d0[4] = {0,0,0,0}, d1[4] = {0,0,0,0};
            float d2[4] = {0,0,0,0}, d3[4] = {0,0,0,0};
            #pragma unroll
            for (int s = 0; s < 8; s++) {
                uint4 bb = up4[9*lr + s];          // (b0,b1) for kt=2s and 2s+1
                int k0 = 2*s, k1 = 2*s + 1;
                int s0 = k0 & 3, s1 = k1 & 3;
                mma16816(d0[s0], d1[s0], d2[s0], d3[s0],
                         af[k0][0], af[k0][1], af[k0][2], af[k0][3], bb.x, bb.y);
                mma16816(d0[s1], d1[s1], d2[s1], d3[s1],
                         af[k1][0], af[k1][1], af[k1][2], af[k1][3], bb.z, bb.w);
            }
            float ktu0 = (d0[0] + d0[1]) + (d0[2] + d0[3]);   // Kt_u[16w+lq]
            float ktu1 = (d2[0] + d2[1]) + (d2[2] + d2[3]);   // Kt_u[16w+lq+8]
            float v0 = __fdividef(sb0, ktu0 + EPS_DIV);
            float v1 = __fdividef(sb1, ktu1 + EPS_DIV);
            if (lr == 0) { s_v[16*w + lq] = v0; s_v[16*w + lq + 8] = v1; }
            publish_perm(vperm, w, lane, v0, v1);
        }
        __syncthreads();

        // ===== matvec2: K_v for rows 16w..+15 (smem K as A, v-perm as B) =====
        {
            float d0[4] = {0,0,0,0}, d1[4] = {0,0,0,0};
            float d2[4] = {0,0,0,0}, d3[4] = {0,0,0,0};
            #pragma unroll
            for (int s = 0; s < 8; s++) {
                uint4 bb = vp4[9*lr + s];
                #pragma unroll
                for (int q = 0; q < 2; q++) {
                    int kt = 2*s + q;
                    int ss = kt & 3;
                    uint32_t a0 = sKw[rA + 8*kt + lr];
                    uint32_t a1 = sKw[rB + 8*kt + lr];
                    uint32_t a2 = sKw[rA + 8*kt + lr + 4];
                    uint32_t a3 = sKw[rB + 8*kt + lr + 4];
                    mma16816(d0[ss], d1[ss], d2[ss], d3[ss],
                             a0, a1, a2, a3,
                             q ? bb.z : bb.x, q ? bb.w : bb.y);
                }
            }
            float kv0 = (d0[0] + d0[1]) + (d0[2] + d0[3]);    // K_v[16w+lq]
            float kv1 = (d2[0] + d2[1]) + (d2[2] + d2[3]);    // K_v[16w+lq+8]
            float u0 = __fdividef(sa0, kv0 + EPS_DIV);
            float u1 = __fdividef(sa1, kv1 + EPS_DIV);
            if (lr == 0) { s_u[16*w + lq] = u0; s_u[16*w + lq + 8] = u1; }
            publish_perm(uperm, w, lane, u0, u1);
        }
        __syncthreads();
    }

    // ---------- ot_cost[b] = sum u[n] K[n,m] v[m] C[n,m] ----------
    float accf = 0.f;
    #pragma unroll 4
    for (int k = 0; k < 32; k++) {
        int idx4 = k * 512 + t;
        float4 c = ((const float4*)Cb)[idx4];
        int lin = idx4 << 2;
        int n = lin >> 8;
        int m = lin & 255;
        uint2 q = *(const uint2*)&sKw[n * ROWW_W + (m >> 1)];
        float un = s_u[n];
        float4 vv = *(const float4*)&s_v[m];
        accf += un * (bflo(q.x) * vv.x * c.x + bfhi(q.x) * vv.y * c.y
                    + bflo(q.y) * vv.z * c.z + bfhi(q.y) * vv.w * c.w);
    }
    #pragma unroll
    for (int o = 16; o; o >>= 1) accf += __shfl_xor_sync(0xffffffffu, accf, o);
    __syncthreads();
    if ((t & 31) == 0) s_ps[t >> 5] = accf;
    __syncthreads();
    if (t == 0) {
        float s = 0.f;
        #pragma unroll
        for (int q = 0; q < 16; q++) s += s_ps[q];
        g_cost[b] = s;
    }
}

__global__ void reduce_kernel(float* __restrict__ out)
{
    __shared__ float sm[8];
    int t = threadIdx.x;
    float s = 0.f;
    #pragma unroll
    for (int i = t; i < B_TOT; i += 256) s += g_cost[i];
    #pragma unroll
    for (int o = 16; o; o >>= 1) s += __shfl_xor_sync(0xffffffffu, s, o);
    if ((t & 31) == 0) sm[t >> 5] = s;
    __syncthreads();
    if (t == 0) {
        float tot = 0.f;
        #pragma unroll
        for (int q = 0; q < 8; q++) tot += sm[q];
        out[0] = tot * (1.0f / B_TOT);
    }
}

extern "C" void kernel_launch(void* const* d_in, const int* in_sizes, int n_in,
                              void* d_out, int out_size)
{
    const float* C  = (const float*)d_in[0];
    const float* mp = (const float*)d_in[1];
    const float* mt = (const float*)d_in[2];
    float* out = (float*)d_out;

    cudaFuncSetAttribute(sinkhorn_kernel,
                         cudaFuncAttributeMaxDynamicSharedMemorySize, SMEM_BYTES);

    sinkhorn_kernel<<<B_TOT, 512, SMEM_BYTES>>>(C, mp, mt);
    reduce_kernel<<<1, 256>>>(out);
}

// round 12
// speedup vs baseline: 6.5387x; 6.0043x over previous
#include <cuda_runtime.h>
#include <cuda_bf16.h>
#include <cstdint>

// Sinkhorn OT, B=1024, N=M=256, <=100 iters. One CTA (512 threads) per batch.
// bf16 HMMA formulation (R8 base, 1035us) + exact-fixed-point early exit:
// the iteration map depends on u only through round_bf16(u); once that image
// stabilizes, all later iterations are bit-identical no-ops -> break.
// Warp w fully owns K-cols 16w..+15 (matvec1, A-frags of K^T in registers)
// and K-rows 16w..+15 (matvec2, A = conflict-free smem words). 2 barriers/iter.
// Vector operands use a permuted 4-copy bf16 layout -> all B-loads LDS.128.

#define B_TOT   1024
#define ITERS   100
#define INV_EPS 10.0f
#define EPS_DIV 1e-8f

#define ROWW_W  132                        // words per padded K row
#define KROW_H  264                        // bf16 per padded K row
#define OFF_A   (256*ROWW_W*4)             // 135168
#define OFF_B   (OFF_A + 1024)
#define OFF_U   (OFF_B + 1024)
#define OFF_V   (OFF_U + 1024)
#define OFF_UP  (OFF_V + 1024)             // uperm: 160 words (640B)
#define OFF_VP  (OFF_UP + 640)             // vperm: 160 words
#define OFF_PS  (OFF_VP + 640)             // 576 floats scratch (+chg flags)
#define SMEM_BYTES (OFF_PS + 2304)         // 142848

__device__ float g_cost[B_TOT];

__device__ __forceinline__ float bflo(unsigned int p) { return __uint_as_float(p << 16); }
__device__ __forceinline__ float bfhi(unsigned int p) { return __uint_as_float(p & 0xffff0000u); }

__device__ __forceinline__ void mma16816(float& d0, float& d1, float& d2, float& d3,
                                         uint32_t a0, uint32_t a1, uint32_t a2, uint32_t a3,
                                         uint32_t b0, uint32_t b1) {
    asm volatile("mma.sync.aligned.m16n8k16.row.col.f32.bf16.bf16.f32 "
                 "{%0,%1,%2,%3}, {%4,%5,%6,%7}, {%8,%9}, {%0,%1,%2,%3};"
                 : "+f"(d0), "+f"(d1), "+f"(d2), "+f"(d3)
                 : "r"(a0), "r"(a1), "r"(a2), "r"(a3), "r"(b0), "r"(b1));
}

// pack K[r][c], K[r+1][c] (bf16 bits) into one b32 (lo = row r)
__device__ __forceinline__ uint32_t ld2k(const unsigned short* sK, int r, int c) {
    uint32_t lo = sK[r * KROW_H + c];
    uint32_t hi = sK[(r + 1) * KROW_H + c];
    return lo | (hi << 16);
}

// Publish x0 (=vec[16w+lq]) / x1 (=vec[16w+lq+8]) into the permuted 4-copy
// bf16 layout: perm[36c + 2w + h] = {vec[16w+2c+8h], vec[16w+2c+8h+1]}.
__device__ __forceinline__ void publish_perm(uint32_t* perm, int w, int lane,
                                             float x0, float x1) {
    int c = (lane >> 1) & 3;
    int h = lane & 1;
    float s00 = __shfl_sync(0xffffffffu, x0, 8*c);
    float s01 = __shfl_sync(0xffffffffu, x0, 8*c + 4);
    float s10 = __shfl_sync(0xffffffffu, x1, 8*c);
    float s11 = __shfl_sync(0xffffffffu, x1, 8*c + 4);
    float lo = h ? s10 : s00;
    float hi = h ? s11 : s01;
    __nv_bfloat162 p = __floats2bfloat162_rn(lo, hi);
    if (lane < 8) perm[36*c + 2*w + h] = *(uint32_t*)&p;
}

extern __shared__ unsigned char smem_raw[];

__global__ __launch_bounds__(512, 1)
void sinkhorn_kernel(const float* __restrict__ C,
                     const float* __restrict__ mass_pred,
                     const float* __restrict__ mass_target)
{
    unsigned short* sK = (unsigned short*)smem_raw;            // 256 x 264 bf16
    const unsigned int* sKw = (const unsigned int*)smem_raw;   // word view
    float* s_a  = (float*)(smem_raw + OFF_A);
    float* s_b  = (float*)(smem_raw + OFF_B);
    float* s_u  = (float*)(smem_raw + OFF_U);
    float* s_v  = (float*)(smem_raw + OFF_V);
    uint32_t* uperm = (uint32_t*)(smem_raw + OFF_UP);
    uint32_t* vperm = (uint32_t*)(smem_raw + OFF_VP);
    const uint4* up4 = (const uint4*)(smem_raw + OFF_UP);
    const uint4* vp4 = (const uint4*)(smem_raw + OFF_VP);
    float* s_ps = (float*)(smem_raw + OFF_PS);
    int*   s_chg = (int*)(smem_raw + OFF_PS);     // reused during iterations

    const int b    = blockIdx.x;
    const int t    = threadIdx.x;
    const int w    = t >> 5;        // warp 0..15
    const int lane = t & 31;
    const int lq   = lane >> 2;     // 0..7
    const int lr   = lane & 3;      // 0..3
    const float* __restrict__ Cb = C + (size_t)b * 65536;

    // ---------- Build K = exp(-C/eps) (bf16, padded rows) ----------
    #pragma unroll 4
    for (int k = 0; k < 32; k++) {
        int idx4 = k * 512 + t;
        float4 c = ((const float4*)Cb)[idx4];
        int lin = idx4 << 2;
        int n = lin >> 8;
        int m = lin & 255;
        __nv_bfloat162 p0 = __floats2bfloat162_rn(__expf(-c.x * INV_EPS),
                                                  __expf(-c.y * INV_EPS));
        __nv_bfloat162 p1 = __floats2bfloat162_rn(__expf(-c.z * INV_EPS),
                                                  __expf(-c.w * INV_EPS));
        *(__nv_bfloat162*)&sK[n * KROW_H + m]     = p0;
        *(__nv_bfloat162*)&sK[n * KROW_H + m + 2] = p1;
    }

    // ---------- Normalize masses (threads 0-255), s_ps scratch ----------
    if (t < 256) {
        float mpv = mass_pred[b * 256 + t];
        float mtv = mass_target[b * 256 + t];
        float sa = mpv, sb = mtv;
        #pragma unroll
        for (int o = 16; o; o >>= 1) {
            sa += __shfl_xor_sync(0xffffffffu, sa, o);
            sb += __shfl_xor_sync(0xffffffffu, sb, o);
        }
        if ((t & 31) == 0) { s_ps[t >> 5] = sa; s_ps[8 + (t >> 5)] = sb; }
        s_ps[64 + t]  = mpv;
        s_ps[320 + t] = mtv;
    }
    // init uperm = all 1.0 bf16 pairs
    if (t < 160) uperm[t] = 0x3F803F80u;
    __syncthreads();
    if (t < 256) {
        float suma = 0.f, sumb = 0.f;
        #pragma unroll
        for (int q = 0; q < 8; q++) { suma += s_ps[q]; sumb += s_ps[8 + q]; }
        s_a[t] = s_ps[64 + t]  / (suma + EPS_DIV);
        s_b[t] = s_ps[320 + t] / (sumb + EPS_DIV);
        s_u[t] = 1.0f;
    }
    __syncthreads();

    // ---------- Persistent A-frags of K^T: warp's 16 cols x all 256 rows ----------
    uint32_t af[16][4];
    #pragma unroll
    for (int kt = 0; kt < 16; kt++) {
        int r = 16*kt + 2*lr;
        int c = 16*w + lq;
        af[kt][0] = ld2k(sK, r,     c);
        af[kt][1] = ld2k(sK, r,     c + 8);
        af[kt][2] = ld2k(sK, r + 8, c);
        af[kt][3] = ld2k(sK, r + 8, c + 8);
    }

    // Hoisted per-thread constants
    const float sa0 = s_a[16*w + lq];
    const float sa1 = s_a[16*w + lq + 8];
    const float sb0 = s_b[16*w + lq];
    const float sb1 = s_b[16*w + lq + 8];
    const int rA = (16*w + lq)     * ROWW_W;
    const int rB = (16*w + lq + 8) * ROWW_W;

    uint32_t pu = 0u;    // previous bf16x2 image of (u0,u1); 0 != any real image

    // ---------- Sinkhorn iterations with exact-fixed-point exit ----------
    for (int it = 0; it < ITERS; it++) {
        // ===== matvec1: Kt_u for cols 16w..+15 (af as A, u-perm as B) =====
        {
            float d0[4] = {0,0,0,0}, d1[4] = {0,0,0,0};
            float d2[4] = {0,0,0,0}, d3[4] = {0,0,0,0};
            #pragma unroll
            for (int s = 0; s < 8; s++) {
                uint4 bb = up4[9*lr + s];          // (b0,b1) for kt=2s and 2s+1
                int k0 = 2*s, k1 = 2*s + 1;
                int s0 = k0 & 3, s1 = k1 & 3;
                mma16816(d0[s0], d1[s0], d2[s0], d3[s0],
                         af[k0][0], af[k0][1], af[k0][2], af[k0][3], bb.x, bb.y);
                mma16816(d0[s1], d1[s1], d2[s1], d3[s1],
                         af[k1][0], af[k1][1], af[k1][2], af[k1][3], bb.z, bb.w);
            }
            float ktu0 = (d0[0] + d0[1]) + (d0[2] + d0[3]);
            float ktu1 = (d2[0] + d2[1]) + (d2[2] + d2[3]);
            float v0 = __fdividef(sb0, ktu0 + EPS_DIV);
            float v1 = __fdividef(sb1, ktu1 + EPS_DIV);
            if (lr == 0) { s_v[16*w + lq] = v0; s_v[16*w + lq + 8] = v1; }
            publish_perm(vperm, w, lane, v0, v1);
        }
        __syncthreads();

        // ===== matvec2: K_v for rows 16w..+15 (smem K as A, v-perm as B) =====
        {
            float d0[4] = {0,0,0,0}, d1[4] = {0,0,0,0};
            float d2[4] = {0,0,0,0}, d3[4] = {0,0,0,0};
            #pragma unroll
            for (int s = 0; s < 8; s++) {
                uint4 bb = vp4[9*lr + s];
                #pragma unroll
                for (int q = 0; q < 2; q++) {
                    int kt = 2*s + q;
                    int ss = kt & 3;
                    uint32_t a0 = sKw[rA + 8*kt + lr];
                    uint32_t a1 = sKw[rB + 8*kt + lr];
                    uint32_t a2 = sKw[rA + 8*kt + lr + 4];
                    uint32_t a3 = sKw[rB + 8*kt + lr + 4];
                    mma16816(d0[ss], d1[ss], d2[ss], d3[ss],
                             a0, a1, a2, a3,
                             q ? bb.z : bb.x, q ? bb.w : bb.y);
                }
            }
            float kv0 = (d0[0] + d0[1]) + (d0[2] + d0[3]);
            float kv1 = (d2[0] + d2[1]) + (d2[2] + d2[3]);
            float u0 = __fdividef(sa0, kv0 + EPS_DIV);
            float u1 = __fdividef(sa1, kv1 + EPS_DIV);
            if (lr == 0) { s_u[16*w + lq] = u0; s_u[16*w + lq + 8] = u1; }
            publish_perm(uperm, w, lane, u0, u1);

            // -- convergence flag: has the bf16 image of u changed? --
            __nv_bfloat162 upk = __floats2bfloat162_rn(u0, u1);
            uint32_t uw = *(uint32_t*)&upk;
            int ch = __any_sync(0xffffffffu, uw != pu);
            pu = uw;
            if (lane == 0) s_chg[w] = ch;
        }
        __syncthreads();

        // CTA-uniform exit decision (bf16 image stable => all later iters no-op)
        {
            int4 c0 = *(const int4*)&s_chg[0];
            int4 c1 = *(const int4*)&s_chg[4];
            int4 c2 = *(const int4*)&s_chg[8];
            int4 c3 = *(const int4*)&s_chg[12];
            int any = (c0.x | c0.y | c0.z | c0.w) | (c1.x | c1.y | c1.z | c1.w)
                    | (c2.x | c2.y | c2.z | c2.w) | (c3.x | c3.y | c3.z | c3.w);
            if (!any) break;
        }
    }
    __syncthreads();

    // ---------- ot_cost[b] = sum u[n] K[n,m] v[m] C[n,m] ----------
    float accf = 0.f;
    #pragma unroll 4
    for (int k = 0; k < 32; k++) {
        int idx4 = k * 512 + t;
        float4 c = ((const float4*)Cb)[idx4];
        int lin = idx4 << 2;
        int n = lin >> 8;
        int m = lin & 255;
        uint2 q = *(const uint2*)&sKw[n * ROWW_W + (m >> 1)];
        float un = s_u[n];
        float4 vv = *(const float4*)&s_v[m];
        accf += un * (bflo(q.x) * vv.x * c.x + bfhi(q.x) * vv.y * c.y
                    + bflo(q.y) * vv.z * c.z + bfhi(q.y) * vv.w * c.w);
    }
    #pragma unroll
    for (int o = 16; o; o >>= 1) accf += __shfl_xor_sync(0xffffffffu, accf, o);
    __syncthreads();
    if ((t & 31) == 0) s_ps[t >> 5] = accf;
    __syncthreads();
    if (t == 0) {
        float s = 0.f;
        #pragma unroll
        for (int q = 0; q < 16; q++) s += s_ps[q];
        g_cost[b] = s;
    }
}

__global__ void reduce_kernel(float* __restrict__ out)
{
    __shared__ float sm[8];
    int t = threadIdx.x;
    float s = 0.f;
    #pragma unroll
    for (int i = t; i < B_TOT; i += 256) s += g_cost[i];
    #pragma unroll
    for (int o = 16; o; o >>= 1) s += __shfl_xor_sync(0xffffffffu, s, o);
    if ((t & 31) == 0) sm[t >> 5] = s;
    __syncthreads();
    if (t == 0) {
        float tot = 0.f;
        #pragma unroll
        for (int q = 0; q < 8; q++) tot += sm[q];
        out[0] = tot * (1.0f / B_TOT);
    }
}

extern "C" void kernel_launch(void* const* d_in, const int* in_sizes, int n_in,
                              void* d_out, int out_size)
{
    const float* C  = (const float*)d_in[0];
    const float* mp = (const float*)d_in[1];
    const float* mt = (const float*)d_in[2];
    float* out = (float*)d_out;

    cudaFuncSetAttribute(sinkhorn_kernel,
                         cudaFuncAttributeMaxDynamicSharedMemorySize, SMEM_BYTES);

    sinkhorn_kernel<<<B_TOT, 512, SMEM_BYTES>>>(C, mp, mt);
    reduce_kernel<<<1, 256>>>(out);
}